// round 1
// baseline (speedup 1.0000x reference)
#include <cuda_runtime.h>

// GaussianVector_box: per box (b,n) splat a 1D gaussian along x (1024) and y (1024).
// Output: [vector_x (B*N*1024 f32)] ++ [vector_y (B*N*1024 f32)] = 256 MB.
// Pure HBM-write bound; only the ~(2r+1)-wide window needs exp, rest is zero.

#define OUT_W 1024
#define OUT_H 1024

__global__ __launch_bounds__(256, 8)
void gv_box_kernel(const float* __restrict__ centers,
                   const float* __restrict__ whs,
                   float* __restrict__ out_x,
                   float* __restrict__ out_y)
{
    const int bn = blockIdx.x;
    const int t  = threadIdx.x;

    // Per-box params (broadcast loads, L1-served)
    const float2 c  = __ldg(((const float2*)centers) + bn);
    const float2 wh = __ldg(((const float2*)whs) + bn);

    // ks = floor(W/2)*2 - 1 ; r = (ks-1)/2 = floor(W/2) - 1 (exact) ; s = floor(r/3)
    const float rw = floorf(wh.x * 0.5f) - 1.0f;
    const float rh = floorf(wh.y * 0.5f) - 1.0f;
    const float sw = floorf(rw / 3.0f);
    const float sh = floorf(rh / 3.0f);

    const bool zero_box = (c.x + c.y + wh.x + wh.y) == 0.0f;

    // SCALE = 4/4 = 1 ; astype(int32) truncates toward zero
    const float x = truncf(c.x);
    const float y = truncf(c.y);

    const float ul0 = x - rw, ul1 = y - rh;
    const float br0 = x + rw + 1.0f, br1 = y + rh + 1.0f;

    const bool in_ul = (ul0 >= 0.0f) & (ul0 <= (float)OUT_W) & (ul1 >= 0.0f) & (ul1 <= (float)OUT_H);
    const bool in_br = (br0 >= 0.0f) & (br0 <= (float)OUT_W) & (br1 >= 0.0f) & (br1 <= (float)OUT_H);

    const bool active = (!zero_box) & (sw != 0.0f) & (sh != 0.0f) & (in_ul | in_br);

    // -1/(2 sigma^2); only consumed when active (sw,sh != 0 then)
    const float kx = -0.5f / (sw * sw);
    const float ky = -0.5f / (sh * sh);

    const float c0 = (float)(t * 4);

    // ---- x row ----
    float4 vx = make_float4(0.f, 0.f, 0.f, 0.f);
    if (active && (c0 + 3.0f) >= ul0 && c0 < br0) {
        #pragma unroll
        for (int j = 0; j < 4; ++j) {
            float p = c0 + (float)j;
            if (p >= ul0 && p < br0) {
                float d = p - x;
                float v = __expf(d * d * kx);
                if (j == 0) vx.x = v; else if (j == 1) vx.y = v;
                else if (j == 2) vx.z = v; else vx.w = v;
            }
        }
    }
    ((float4*)(out_x + (size_t)bn * OUT_W))[t] = vx;

    // ---- y row ----
    float4 vy = make_float4(0.f, 0.f, 0.f, 0.f);
    if (active && (c0 + 3.0f) >= ul1 && c0 < br1) {
        #pragma unroll
        for (int j = 0; j < 4; ++j) {
            float p = c0 + (float)j;
            if (p >= ul1 && p < br1) {
                float d = p - y;
                float v = __expf(d * d * ky);
                if (j == 0) vy.x = v; else if (j == 1) vy.y = v;
                else if (j == 2) vy.z = v; else vy.w = v;
            }
        }
    }
    ((float4*)(out_y + (size_t)bn * OUT_H))[t] = vy;
}

extern "C" void kernel_launch(void* const* d_in, const int* in_sizes, int n_in,
                              void* d_out, int out_size)
{
    const float* centers = (const float*)d_in[0];  // [B,N,2]
    const float* whs     = (const float*)d_in[1];  // [B,N,2]
    float* out = (float*)d_out;

    const int BN = in_sizes[0] / 2;                // 128*256 = 32768
    float* out_x = out;
    float* out_y = out + (size_t)BN * OUT_W;

    gv_box_kernel<<<BN, 256>>>(centers, whs, out_x, out_y);
}

// round 3
// speedup vs baseline: 1.3438x; 1.3438x over previous
#include <cuda_runtime.h>
#include <math_constants.h>

// GaussianVector_box: per box (b,n) splat a 1D gaussian along x (1024) and y (1024).
// Output: [vector_x (B*N*1024 f32)] ++ [vector_y (B*N*1024 f32)] = 256 MB -> pure
// HBM-write bound. Box params (4 divisions + floors + bounds logic) computed ONCE
// per CTA in smem instead of 256x redundantly per thread; stores are streaming.

#define OUT_W 1024
#define OUT_H 1024

__global__ __launch_bounds__(256, 8)
void gv_box_kernel(const float* __restrict__ centers,
                   const float* __restrict__ whs,
                   float* __restrict__ out_x,
                   float* __restrict__ out_y)
{
    __shared__ float4 sp[2];   // sp[0] = {x, ul0, br0, kx}, sp[1] = {y, ul1, br1, ky}

    const int bn = blockIdx.x;
    const int t  = threadIdx.x;

    if (t == 0) {
        const float2 c  = __ldg(((const float2*)centers) + bn);
        const float2 wh = __ldg(((const float2*)whs) + bn);

        // ks = floor(W/2)*2 - 1 ; r = (ks-1)/2 = floor(W/2) - 1 (exact) ; s = floor(r/3)
        const float rw = floorf(wh.x * 0.5f) - 1.0f;
        const float rh = floorf(wh.y * 0.5f) - 1.0f;
        const float sw = floorf(rw / 3.0f);
        const float sh = floorf(rh / 3.0f);

        const bool zero_box = (c.x + c.y + wh.x + wh.y) == 0.0f;

        // SCALE = 1 ; astype(int32) truncates toward zero
        const float x = truncf(c.x);
        const float y = truncf(c.y);

        float ul0 = x - rw, ul1 = y - rh;
        float br0 = x + rw + 1.0f, br1 = y + rh + 1.0f;

        const bool in_ul = (ul0 >= 0.0f) & (ul0 <= (float)OUT_W) &
                           (ul1 >= 0.0f) & (ul1 <= (float)OUT_H);
        const bool in_br = (br0 >= 0.0f) & (br0 <= (float)OUT_W) &
                           (br1 >= 0.0f) & (br1 <= (float)OUT_H);

        const bool active = (!zero_box) & (sw != 0.0f) & (sh != 0.0f) & (in_ul | in_br);

        if (!active) {   // encode as empty windows -> whole rows stay zero
            ul0 = CUDART_INF_F;  br0 = -CUDART_INF_F;
            ul1 = CUDART_INF_F;  br1 = -CUDART_INF_F;
        }

        // -1/(2 sigma^2); only consumed by lanes inside a (then-valid) window
        const float kx = -0.5f / (sw * sw);
        const float ky = -0.5f / (sh * sh);

        sp[0] = make_float4(x, ul0, br0, kx);
        sp[1] = make_float4(y, ul1, br1, ky);
    }
    __syncthreads();

    const float4 Px = sp[0];
    const float4 Py = sp[1];
    const float  c0 = (float)(t << 2);

    // ---- x row ----
    float4 vx = make_float4(0.f, 0.f, 0.f, 0.f);
    if ((c0 + 3.0f) >= Px.y && c0 < Px.z) {
        #pragma unroll
        for (int j = 0; j < 4; ++j) {
            float p = c0 + (float)j;
            if (p >= Px.y && p < Px.z) {
                float d = p - Px.x;
                float v = __expf(d * d * Px.w);
                if (j == 0) vx.x = v; else if (j == 1) vx.y = v;
                else if (j == 2) vx.z = v; else vx.w = v;
            }
        }
    }

    // ---- y row ----
    float4 vy = make_float4(0.f, 0.f, 0.f, 0.f);
    if ((c0 + 3.0f) >= Py.y && c0 < Py.z) {
        #pragma unroll
        for (int j = 0; j < 4; ++j) {
            float p = c0 + (float)j;
            if (p >= Py.y && p < Py.z) {
                float d = p - Py.x;
                float v = __expf(d * d * Py.w);
                if (j == 0) vy.x = v; else if (j == 1) vy.y = v;
                else if (j == 2) vy.z = v; else vy.w = v;
            }
        }
    }

    // Streaming (evict-first) 128-bit stores — 268 MB write-once stream.
    __stcs(((float4*)(out_x + (size_t)bn * OUT_W)) + t, vx);
    __stcs(((float4*)(out_y + (size_t)bn * OUT_H)) + t, vy);
}

extern "C" void kernel_launch(void* const* d_in, const int* in_sizes, int n_in,
                              void* d_out, int out_size)
{
    const float* centers = (const float*)d_in[0];  // [B,N,2]
    const float* whs     = (const float*)d_in[1];  // [B,N,2]
    float* out = (float*)d_out;

    const int BN = in_sizes[0] / 2;                // 128*256 = 32768
    float* out_x = out;
    float* out_y = out + (size_t)BN * OUT_W;

    gv_box_kernel<<<BN, 256>>>(centers, whs, out_x, out_y);
}